// round 2
// baseline (speedup 1.0000x reference)
#include <cuda_runtime.h>
#include <math.h>
#include <float.h>

#define N_ANCH   172032
#define MAX_OUT  200
#define NMS_TH   0.4f
#define NBINS    65536
#define TARGET   2048u
#define CAP      4096
#define NPW      4096   // bitonic width (pow2 >= CAP)

// ---------------- static device scratch ----------------
struct Ctl { unsigned ncand; unsigned thresh_u; unsigned truncated; unsigned fallback; };
__device__ Ctl      g_ctl;
__device__ unsigned g_hist[NBINS];
__device__ float    g_scores[N_ANCH];
__device__ unsigned long long g_ckey[CAP];
__device__ int      g_sel_idx[MAX_OUT];
__device__ int      g_sel_valid[MAX_OUT];

// ---------------- decode helper (matches reference _decode) ----------------
__device__ __forceinline__ void decode_box(const float4& rg, const float4& an,
                                           float& y1, float& x1, float& y2, float& x2,
                                           float& ar) {
    float dx = rg.x * 0.1f, dy = rg.y * 0.1f, dw = rg.z * 0.2f, dh = rg.w * 0.2f;
    float xc = dx * an.z + an.x;
    float yc = dy * an.w + an.y;
    float w  = expf(dw) * an.z;
    float h  = expf(dh) * an.w;
    y1 = yc - 0.5f * h;  x1 = xc - 0.5f * w;
    y2 = yc + 0.5f * h;  x2 = xc + 0.5f * w;
    ar = (y2 - y1) * (x2 - x1);
}

__device__ __forceinline__ float iou_f(float ay1, float ax1, float ay2, float ax2, float aar,
                                       float by1, float bx1, float by2, float bx2, float bar) {
    float ih = fmaxf(fminf(ay2, by2) - fmaxf(ay1, by1), 0.f);
    float iw = fmaxf(fminf(ax2, bx2) - fmaxf(ax1, bx1), 0.f);
    float inter = ih * iw;
    return inter / (aar + bar - inter + 1e-12f);
}

// ---------------- 1) histogram of candidate scores ----------------
__global__ void hist_kernel(const float* __restrict__ cls, int n) {
    int i = blockIdx.x * blockDim.x + threadIdx.x;
    if (i >= n) return;
    float s = __ldg(&cls[2 * i + 1]);
    bool ok = (s > NMS_TH);
    g_scores[i] = ok ? s : -INFINITY;
    if (ok) {
        unsigned u = __float_as_uint(s) ^ 0x80000000u;   // s>0.4 => positive
        atomicAdd(&g_hist[u >> 16], 1u);
    }
}

// ---------------- 2) find bit-threshold capturing top >= TARGET ----------------
__global__ __launch_bounds__(1024) void thresh_kernel() {
    __shared__ unsigned csum[1024];
    unsigned t = threadIdx.x;
    unsigned sum = 0;
    for (int k = 0; k < 64; k++) sum += g_hist[t * 64 + k];
    unsigned mysum = sum;
    csum[t] = sum;
    __syncthreads();
    // suffix sums (Hillis-Steele)
    for (int off = 1; off < 1024; off <<= 1) {
        unsigned v = (t + off < 1024) ? csum[t + off] : 0u;
        __syncthreads();
        csum[t] += v;
        __syncthreads();
    }
    unsigned total = csum[0];
    unsigned above = (t < 1023) ? csum[t + 1] : 0u;   // sum of all higher chunks
    if (above < TARGET && csum[t] >= TARGET) {
        unsigned run = above;
        for (int b = 63; b >= 0; b--) {
            run += g_hist[t * 64 + b];
            if (run >= TARGET) {
                g_ctl.thresh_u = (unsigned)(t * 64 + b) << 16;
                g_ctl.truncated = (run < total) ? 1u : 0u;
                break;
            }
        }
    }
    (void)mysum;
}

// ---------------- 3) compact top candidates as 64-bit keys ----------------
__global__ void compact_kernel(int n) {
    int i = blockIdx.x * blockDim.x + threadIdx.x;
    if (i >= n) return;
    float sc = g_scores[i];
    if (sc > -INFINITY) {
        unsigned u = __float_as_uint(sc) ^ 0x80000000u;
        if (u >= g_ctl.thresh_u) {
            unsigned pos = atomicAdd(&g_ctl.ncand, 1u);
            if (pos < CAP)
                g_ckey[pos] = ((unsigned long long)u << 32) | (unsigned)(~(unsigned)i);
        }
    }
}

// ---------------- 4) fused bitonic sort + greedy NMS (single block) ----------------
// dynamic smem layout
#define SM_KEYS   0
#define SM_Y1     (SM_KEYS + NPW * 8)
#define SM_X1     (SM_Y1  + NPW * 4)
#define SM_Y2     (SM_X1  + NPW * 4)
#define SM_X2     (SM_Y2  + NPW * 4)
#define SM_AR     (SM_X2  + NPW * 4)
#define SM_IDX    (SM_AR  + NPW * 4)
#define SM_MASK   (SM_IDX + NPW * 4)
#define SM_MISC   (SM_MASK + 128 * 4)
#define SM_TOTAL  (SM_MISC + 64)

__global__ __launch_bounds__(1024) void sortnms_kernel(const float* __restrict__ reg,
                                                       const float* __restrict__ anch) {
    extern __shared__ unsigned char smem[];
    unsigned long long* keys = (unsigned long long*)(smem + SM_KEYS);
    float* sy1 = (float*)(smem + SM_Y1);
    float* sx1 = (float*)(smem + SM_X1);
    float* sy2 = (float*)(smem + SM_Y2);
    float* sx2 = (float*)(smem + SM_X2);
    float* sar = (float*)(smem + SM_AR);
    int*   sidx = (int*)(smem + SM_IDX);
    unsigned* maskw = (unsigned*)(smem + SM_MASK);
    int* s_sel = (int*)(smem + SM_MISC);

    const int t = threadIdx.x;
    unsigned nc = g_ctl.ncand;
    if (nc > CAP) {               // degenerate overflow: punt to exact fallback
        if (t == 0) g_ctl.fallback = 1;
        return;
    }

    // load + pad
    for (int c = t; c < NPW; c += 1024)
        keys[c] = (c < (int)nc) ? g_ckey[c] : 0ULL;
    __syncthreads();

    // bitonic sort, descending
    for (int k = 2; k <= NPW; k <<= 1) {
        for (int j = k >> 1; j > 0; j >>= 1) {
            for (int i = t; i < NPW; i += 1024) {
                int l = i ^ j;
                if (l > i) {
                    unsigned long long a = keys[i], b = keys[l];
                    bool desc = ((i & k) == 0);
                    if (desc ? (a < b) : (a > b)) { keys[i] = b; keys[l] = a; }
                }
            }
            __syncthreads();
        }
    }

    // decode boxes of candidates (each thread owns 4, strided)
    bool alive[4];
    float ry1[4], rx1[4], ry2[4], rx2[4], rar[4];
#pragma unroll
    for (int m = 0; m < 4; m++) {
        int c = t + (m << 10);
        alive[m] = (c < (int)nc);
        if (alive[m]) {
            int idx = (int)(~(unsigned)(keys[c] & 0xFFFFFFFFull));
            sidx[c] = idx;
            float4 rg = __ldg(reinterpret_cast<const float4*>(reg) + idx);
            float4 an = __ldg(reinterpret_cast<const float4*>(anch) + idx);
            decode_box(rg, an, ry1[m], rx1[m], ry2[m], rx2[m], rar[m]);
            sy1[c] = ry1[m]; sx1[c] = rx1[m]; sy2[c] = ry2[m]; sx2[c] = rx2[m]; sar[c] = rar[m];
        }
    }
    // alive bitmask
    if (t < 128) {
        int cnt = (int)nc - t * 32;
        cnt = cnt < 0 ? 0 : (cnt > 32 ? 32 : cnt);
        maskw[t] = (cnt == 32) ? 0xFFFFFFFFu : ((cnt == 0) ? 0u : ((1u << cnt) - 1u));
    }
    __syncthreads();

    // greedy selection
    int nsel = 0;
    int cw = 0;   // word cursor (t0 only)
    while (nsel < MAX_OUT) {
        if (t == 0) {
            int sel = -1;
            while (cw < 128 && maskw[cw] == 0u) cw++;
            if (cw < 128) sel = (cw << 5) + __ffs(maskw[cw]) - 1;
            s_sel[0] = sel;
        }
        __syncthreads();
        int sel = s_sel[0];
        if (sel < 0) break;
        float by1 = sy1[sel], bx1 = sx1[sel], by2 = sy2[sel], bx2 = sx2[sel], bar = sar[sel];
        if (t == 0) g_sel_idx[nsel] = sidx[sel];
#pragma unroll
        for (int m = 0; m < 4; m++) {
            if (alive[m]) {
                float iou = iou_f(ry1[m], rx1[m], ry2[m], rx2[m], rar[m],
                                  by1, bx1, by2, bx2, bar);
                if (iou > NMS_TH) {   // self-IoU==1 removes the selected box too
                    alive[m] = false;
                    int c = t + (m << 10);
                    atomicAnd(&maskw[c >> 5], ~(1u << (c & 31)));
                }
            }
        }
        nsel++;
        __syncthreads();
    }

    if (t == 0 && nsel < MAX_OUT && g_ctl.truncated) g_ctl.fallback = 1;
    for (int j = t; j < MAX_OUT; j += 1024) {
        g_sel_valid[j] = (j < nsel) ? 1 : 0;
        if (j >= nsel) g_sel_idx[j] = 0;
    }
}

// ---------------- 5) exact fallback (normally a no-op) ----------------
__global__ __launch_bounds__(1024) void fallback_kernel(const float* __restrict__ reg,
                                                        const float* __restrict__ anch, int n) {
    if (g_ctl.fallback == 0) return;
    __shared__ float red_s[1024];
    __shared__ int   red_i[1024];
    const int t = threadIdx.x;
    for (int it = 0; it < MAX_OUT; it++) {
        float best = -INFINITY; int bi = 0;
        for (int j = t; j < n; j += 1024) {
            float v = g_scores[j];
            if (v > best) { best = v; bi = j; }
        }
        red_s[t] = best; red_i[t] = bi;
        __syncthreads();
        for (int s = 512; s > 0; s >>= 1) {
            if (t < s) {
                float vo = red_s[t + s]; int io = red_i[t + s];
                if (vo > red_s[t] || (vo == red_s[t] && io < red_i[t])) {
                    red_s[t] = vo; red_i[t] = io;
                }
            }
            __syncthreads();
        }
        int i = red_i[0];
        float v = red_s[0];
        bool valid = (v > -INFINITY);
        // decode selected box (all threads, broadcast loads)
        float4 rgi = __ldg(reinterpret_cast<const float4*>(reg) + i);
        float4 ani = __ldg(reinterpret_cast<const float4*>(anch) + i);
        float by1, bx1, by2, bx2, bar;
        decode_box(rgi, ani, by1, bx1, by2, bx2, bar);
        if (valid) {
            for (int j = t; j < n; j += 1024) {
                if (g_scores[j] > -INFINITY) {
                    float4 rg = __ldg(reinterpret_cast<const float4*>(reg) + j);
                    float4 an = __ldg(reinterpret_cast<const float4*>(anch) + j);
                    float y1, x1, y2, x2, ar;
                    decode_box(rg, an, y1, x1, y2, x2, ar);
                    float iou = iou_f(y1, x1, y2, x2, ar, by1, bx1, by2, bx2, bar);
                    if (iou > NMS_TH) g_scores[j] = -INFINITY;
                }
            }
        }
        if (t == 0) { g_sel_idx[it] = i; g_sel_valid[it] = valid ? 1 : 0; }
        __syncthreads();
    }
}

// ---------------- 6) gather outputs ----------------
__global__ void gather_kernel(const float* __restrict__ reg,
                              const float* __restrict__ lnd,
                              const float* __restrict__ anch,
                              float* __restrict__ out) {
    int t = blockIdx.x * blockDim.x + threadIdx.x;
    if (t >= MAX_OUT) return;
    int idx = g_sel_idx[t];
    float m = g_sel_valid[t] ? 1.f : 0.f;

    float4 rg = __ldg(reinterpret_cast<const float4*>(reg) + idx);
    float4 an = __ldg(reinterpret_cast<const float4*>(anch) + idx);
    float y1, x1, y2, x2, ar;
    decode_box(rg, an, y1, x1, y2, x2, ar);

    out[4 * t + 0] = y1 * m;
    out[4 * t + 1] = x1 * m;
    out[4 * t + 2] = y2 * m;
    out[4 * t + 3] = x2 * m;

    const float* lp = lnd + 10 * idx;
    float* op = out + 4 * MAX_OUT + 10 * t;
#pragma unroll
    for (int k = 0; k < 5; k++) {
        float lx = lp[2 * k]     * 0.1f * an.z + an.x;
        float ly = lp[2 * k + 1] * 0.1f * an.w + an.y;
        op[2 * k]     = lx * m;
        op[2 * k + 1] = ly * m;
    }
}

// ---------------- launch ----------------
extern "C" void kernel_launch(void* const* d_in, const int* in_sizes, int n_in,
                              void* d_out, int out_size) {
    const float* cls  = (const float*)d_in[0];
    const float* reg  = (const float*)d_in[1];
    const float* lnd  = (const float*)d_in[2];
    const float* anch = (const float*)d_in[3];

    int n = in_sizes[0] / 2;
    if (n > N_ANCH) n = N_ANCH;

    void *hist_p = nullptr, *ctl_p = nullptr;
    cudaGetSymbolAddress(&hist_p, g_hist);
    cudaGetSymbolAddress(&ctl_p, g_ctl);

    static bool attr_set = false;
    (void)attr_set;
    cudaFuncSetAttribute(sortnms_kernel, cudaFuncAttributeMaxDynamicSharedMemorySize, SM_TOTAL);

    cudaMemsetAsync(hist_p, 0, NBINS * sizeof(unsigned));
    cudaMemsetAsync(ctl_p, 0, sizeof(Ctl));

    hist_kernel<<<(n + 255) / 256, 256>>>(cls, n);
    thresh_kernel<<<1, 1024>>>();
    compact_kernel<<<(n + 255) / 256, 256>>>(n);
    sortnms_kernel<<<1, 1024, SM_TOTAL>>>(reg, anch);
    fallback_kernel<<<1, 1024>>>(reg, anch, n);
    gather_kernel<<<1, 256>>>(reg, lnd, anch, (float*)d_out);
}

// round 3
// speedup vs baseline: 2.5083x; 2.5083x over previous
#include <cuda_runtime.h>
#include <math.h>
#include <float.h>

#define N_ANCH   172032
#define MAX_OUT  200
#define NMS_TH   0.4f
#define NBINS    65536
#define TARGET   768u
#define CAP      2048     // compacted key storage / bitonic width
#define M        1024     // NMS working set (top-M sorted candidates)

// ---------------- static device scratch ----------------
struct Ctl { unsigned ncand; unsigned thresh_u; unsigned truncated; unsigned fallback; unsigned nc; };
__device__ Ctl      g_ctl;
__device__ unsigned g_hist[NBINS];
__device__ float    g_scores[N_ANCH];
__device__ unsigned long long g_ckey[CAP];
__device__ float4   g_sb4[M];          // sorted decoded boxes (y1,x1,y2,x2)
__device__ float    g_sar[M];          // areas
__device__ int      g_sidx[M];         // original anchor index
__device__ unsigned g_supp[M * 32];    // suppression bitmask matrix
__device__ int      g_sel_idx[MAX_OUT];
__device__ int      g_sel_valid[MAX_OUT];

// ---------------- decode helper (matches reference _decode) ----------------
__device__ __forceinline__ void decode_box(const float4& rg, const float4& an,
                                           float& y1, float& x1, float& y2, float& x2,
                                           float& ar) {
    float dx = rg.x * 0.1f, dy = rg.y * 0.1f, dw = rg.z * 0.2f, dh = rg.w * 0.2f;
    float xc = dx * an.z + an.x;
    float yc = dy * an.w + an.y;
    float w  = expf(dw) * an.z;
    float h  = expf(dh) * an.w;
    y1 = yc - 0.5f * h;  x1 = xc - 0.5f * w;
    y2 = yc + 0.5f * h;  x2 = xc + 0.5f * w;
    ar = (y2 - y1) * (x2 - x1);
}

__device__ __forceinline__ float iou_f(float ay1, float ax1, float ay2, float ax2, float aar,
                                       float by1, float bx1, float by2, float bx2, float bar) {
    float ih = fmaxf(fminf(ay2, by2) - fmaxf(ay1, by1), 0.f);
    float iw = fmaxf(fminf(ax2, bx2) - fmaxf(ax1, bx1), 0.f);
    float inter = ih * iw;
    return inter / (aar + bar - inter + 1e-12f);
}

// ---------------- 1) histogram of candidate scores ----------------
__global__ void hist_kernel(const float* __restrict__ cls, int n) {
    int i = blockIdx.x * blockDim.x + threadIdx.x;
    if (i >= n) return;
    float s = __ldg(&((const float2*)cls)[i].y);
    bool ok = (s > NMS_TH);
    g_scores[i] = ok ? s : -INFINITY;
    if (ok) {
        unsigned u = __float_as_uint(s) ^ 0x80000000u;   // s>0.4 => positive float
        atomicAdd(&g_hist[u >> 16], 1u);
    }
}

// ---------------- 2) bit-threshold capturing top >= TARGET ----------------
__global__ __launch_bounds__(1024) void thresh_kernel() {
    __shared__ unsigned csum[1024];
    unsigned t = threadIdx.x;
    unsigned sum = 0;
    for (int k = 0; k < 64; k++) sum += g_hist[t * 64 + k];
    csum[t] = sum;
    __syncthreads();
    for (int off = 1; off < 1024; off <<= 1) {           // suffix sums
        unsigned v = (t + off < 1024) ? csum[t + off] : 0u;
        __syncthreads();
        csum[t] += v;
        __syncthreads();
    }
    unsigned total = csum[0];
    unsigned above = (t < 1023) ? csum[t + 1] : 0u;
    if (above < TARGET && csum[t] >= TARGET) {
        unsigned run = above;
        for (int b = 63; b >= 0; b--) {
            run += g_hist[t * 64 + b];
            if (run >= TARGET) {
                g_ctl.thresh_u  = (unsigned)(t * 64 + b) << 16;
                g_ctl.truncated = (run < total) ? 1u : 0u;
                break;
            }
        }
    }
}

// ---------------- 3) compact top candidates as 64-bit keys ----------------
__global__ void compact_kernel(int n) {
    int i = blockIdx.x * blockDim.x + threadIdx.x;
    if (i >= n) return;
    float sc = g_scores[i];
    if (sc > -INFINITY) {
        unsigned u = __float_as_uint(sc) ^ 0x80000000u;
        if (u >= g_ctl.thresh_u) {
            unsigned pos = atomicAdd(&g_ctl.ncand, 1u);
            if (pos < CAP)
                g_ckey[pos] = ((unsigned long long)u << 32) | (unsigned)(~(unsigned)i);
        }
    }
}

// ---------------- 4) bitonic sort (2048) + decode top-M (single block) ----------------
__global__ __launch_bounds__(1024) void sortdecode_kernel(const float* __restrict__ reg,
                                                          const float* __restrict__ anch) {
    __shared__ unsigned long long keys[CAP];
    const int t = threadIdx.x;
    unsigned nc_all = g_ctl.ncand;
    if (nc_all > CAP) {                 // stored subset would be arbitrary -> exact fallback
        if (t == 0) { g_ctl.fallback = 1; g_ctl.nc = 0; }
        return;
    }
    keys[t]        = (t        < (int)nc_all) ? g_ckey[t]        : 0ULL;
    keys[t + 1024] = (t + 1024 < (int)nc_all) ? g_ckey[t + 1024] : 0ULL;
    __syncthreads();

    for (int k = 2; k <= CAP; k <<= 1) {
        for (int j = k >> 1; j > 0; j >>= 1) {
            #pragma unroll
            for (int rep = 0; rep < 2; rep++) {
                int i = t + (rep << 10);
                int l = i ^ j;
                if (l > i) {
                    unsigned long long a = keys[i], b = keys[l];
                    bool desc = ((i & k) == 0);
                    if (desc ? (a < b) : (a > b)) { keys[i] = b; keys[l] = a; }
                }
            }
            __syncthreads();
        }
    }

    unsigned nc = nc_all < M ? nc_all : M;
    if (t == 0) {
        g_ctl.nc = nc;
        if (nc_all > M) g_ctl.truncated = 1;
    }
    if (t < M) {
        if (t < (int)nc) {
            int idx = (int)(~(unsigned)(keys[t] & 0xFFFFFFFFull));
            g_sidx[t] = idx;
            float4 rg = __ldg(reinterpret_cast<const float4*>(reg) + idx);
            float4 an = __ldg(reinterpret_cast<const float4*>(anch) + idx);
            float y1, x1, y2, x2, ar;
            decode_box(rg, an, y1, x1, y2, x2, ar);
            g_sb4[t] = make_float4(y1, x1, y2, x2);
            g_sar[t] = ar;
        } else {
            g_sidx[t] = 0;
            g_sb4[t] = make_float4(0.f, 0.f, 0.f, 0.f);   // degenerate: IoU==0 vs anything
            g_sar[t] = 0.f;
        }
    }
}

// ---------------- 5) pairwise suppression bitmask matrix (multi-SM) ----------------
__global__ __launch_bounds__(256) void pairs_kernel() {
    int gid = blockIdx.x * 256 + threadIdx.x;   // 1024 rows x 32 words
    int i = gid >> 5;                           // row (uniform per warp)
    int w = gid & 31;                           // word within row
    float4 bi = g_sb4[i];
    float ari = g_sar[i];
    unsigned word = 0;
    #pragma unroll 8
    for (int jj = 0; jj < 32; jj++) {
        int j = (w << 5) + jj;
        float4 bj = g_sb4[j];
        float iou = iou_f(bi.x, bi.y, bi.z, bi.w, ari, bj.x, bj.y, bj.z, bj.w, g_sar[j]);
        if (iou > NMS_TH) word |= (1u << jj);
    }
    g_supp[(i << 5) + w] = word;
}

// ---------------- 6) greedy: preload matrix to smem, warp-serial selection ----------------
__global__ __launch_bounds__(1024) void greedy_kernel() {
    extern __shared__ unsigned ssup[];          // M*32 = 32768 words = 128 KB
    const int t = threadIdx.x;
    if (g_ctl.fallback) return;
    for (int k = t; k < M * 32; k += 1024) ssup[k] = g_supp[k];
    __syncthreads();

    if (t < 32) {
        const unsigned FULL = 0xFFFFFFFFu;
        int lane = t;
        int nc = (int)g_ctl.nc;
        int rem = nc - lane * 32;
        unsigned valid = (rem >= 32) ? 0xFFFFFFFFu : ((rem <= 0) ? 0u : ((1u << rem) - 1u));
        unsigned removed = 0;
        int nsel = 0;
        while (nsel < MAX_OUT) {
            unsigned alivew = valid & ~removed;
            unsigned bal = __ballot_sync(FULL, alivew != 0u);
            if (!bal) break;
            int src = __ffs(bal) - 1;
            unsigned w0 = __shfl_sync(FULL, alivew, src);
            int i = (src << 5) + __ffs(w0) - 1;
            if (lane == 0) g_sel_idx[nsel] = g_sidx[i];
            removed |= ssup[(i << 5) + lane];    // self bit set (IoU=1) -> i removed
            nsel++;
        }
        if (lane == 0 && nsel < MAX_OUT && g_ctl.truncated) g_ctl.fallback = 1;
        for (int j = lane; j < MAX_OUT; j += 32) {
            g_sel_valid[j] = (j < nsel) ? 1 : 0;
            if (j >= nsel) g_sel_idx[j] = 0;
        }
    }
}

// ---------------- 7) exact fallback (normally a no-op) ----------------
__global__ __launch_bounds__(1024) void fallback_kernel(const float* __restrict__ reg,
                                                        const float* __restrict__ anch, int n) {
    if (g_ctl.fallback == 0) return;
    __shared__ float red_s[1024];
    __shared__ int   red_i[1024];
    const int t = threadIdx.x;
    for (int it = 0; it < MAX_OUT; it++) {
        float best = -INFINITY; int bi = 0;
        for (int j = t; j < n; j += 1024) {
            float v = g_scores[j];
            if (v > best) { best = v; bi = j; }
        }
        red_s[t] = best; red_i[t] = bi;
        __syncthreads();
        for (int s = 512; s > 0; s >>= 1) {
            if (t < s) {
                float vo = red_s[t + s]; int io = red_i[t + s];
                if (vo > red_s[t] || (vo == red_s[t] && io < red_i[t])) {
                    red_s[t] = vo; red_i[t] = io;
                }
            }
            __syncthreads();
        }
        int i = red_i[0];
        bool valid = (red_s[0] > -INFINITY);
        float4 rgi = __ldg(reinterpret_cast<const float4*>(reg) + i);
        float4 ani = __ldg(reinterpret_cast<const float4*>(anch) + i);
        float by1, bx1, by2, bx2, bar;
        decode_box(rgi, ani, by1, bx1, by2, bx2, bar);
        if (valid) {
            for (int j = t; j < n; j += 1024) {
                if (g_scores[j] > -INFINITY) {
                    float4 rg = __ldg(reinterpret_cast<const float4*>(reg) + j);
                    float4 an = __ldg(reinterpret_cast<const float4*>(anch) + j);
                    float y1, x1, y2, x2, ar;
                    decode_box(rg, an, y1, x1, y2, x2, ar);
                    if (iou_f(y1, x1, y2, x2, ar, by1, bx1, by2, bx2, bar) > NMS_TH)
                        g_scores[j] = -INFINITY;
                }
            }
        }
        if (t == 0) { g_sel_idx[it] = i; g_sel_valid[it] = valid ? 1 : 0; }
        __syncthreads();
    }
}

// ---------------- 8) gather outputs ----------------
__global__ void gather_kernel(const float* __restrict__ reg,
                              const float* __restrict__ lnd,
                              const float* __restrict__ anch,
                              float* __restrict__ out) {
    int t = blockIdx.x * blockDim.x + threadIdx.x;
    if (t >= MAX_OUT) return;
    int idx = g_sel_idx[t];
    float m = g_sel_valid[t] ? 1.f : 0.f;

    float4 rg = __ldg(reinterpret_cast<const float4*>(reg) + idx);
    float4 an = __ldg(reinterpret_cast<const float4*>(anch) + idx);
    float y1, x1, y2, x2, ar;
    decode_box(rg, an, y1, x1, y2, x2, ar);

    out[4 * t + 0] = y1 * m;
    out[4 * t + 1] = x1 * m;
    out[4 * t + 2] = y2 * m;
    out[4 * t + 3] = x2 * m;

    const float* lp = lnd + 10 * idx;
    float* op = out + 4 * MAX_OUT + 10 * t;
#pragma unroll
    for (int k = 0; k < 5; k++) {
        float lx = lp[2 * k]     * 0.1f * an.z + an.x;
        float ly = lp[2 * k + 1] * 0.1f * an.w + an.y;
        op[2 * k]     = lx * m;
        op[2 * k + 1] = ly * m;
    }
}

// ---------------- launch ----------------
extern "C" void kernel_launch(void* const* d_in, const int* in_sizes, int n_in,
                              void* d_out, int out_size) {
    const float* cls  = (const float*)d_in[0];
    const float* reg  = (const float*)d_in[1];
    const float* lnd  = (const float*)d_in[2];
    const float* anch = (const float*)d_in[3];

    int n = in_sizes[0] / 2;
    if (n > N_ANCH) n = N_ANCH;

    void *hist_p = nullptr, *ctl_p = nullptr;
    cudaGetSymbolAddress(&hist_p, g_hist);
    cudaGetSymbolAddress(&ctl_p, g_ctl);

    cudaFuncSetAttribute(greedy_kernel, cudaFuncAttributeMaxDynamicSharedMemorySize,
                         M * 32 * sizeof(unsigned));

    cudaMemsetAsync(hist_p, 0, NBINS * sizeof(unsigned));
    cudaMemsetAsync(ctl_p, 0, sizeof(Ctl));

    hist_kernel<<<(n + 255) / 256, 256>>>(cls, n);
    thresh_kernel<<<1, 1024>>>();
    compact_kernel<<<(n + 255) / 256, 256>>>(n);
    sortdecode_kernel<<<1, 1024>>>(reg, anch);
    pairs_kernel<<<M * 32 / 256, 256>>>();
    greedy_kernel<<<1, 1024, M * 32 * sizeof(unsigned)>>>();
    fallback_kernel<<<1, 1024>>>(reg, anch, n);
    gather_kernel<<<1, 256>>>(reg, lnd, anch, (float*)d_out);
}

// round 4
// speedup vs baseline: 4.0242x; 1.6044x over previous
#include <cuda_runtime.h>
#include <math.h>

#define N_ANCH   172032
#define MAX_OUT  200
#define NMS_TH   0.4f
#define NBINS    4096
#define SHIFT    20
#define TARGET   512u
#define CAP      4096
#define M        512

// ---------------- static device scratch ----------------
struct Ctl { unsigned ncand, thresh_u, truncated, fallback, nc; };
__device__ Ctl      g_ctl;                 // zero-init (BSS); reset each run by thresh_kernel
__device__ unsigned g_hist[NBINS];         // self-cleaning (zeroed at end of thresh_kernel)
__device__ unsigned long long g_ckey[CAP];
__device__ float4   g_sb4[M];              // sorted decoded boxes (y1,x1,y2,x2)
__device__ float    g_sar[M];
__device__ int      g_sidx[M];
__device__ unsigned g_supp[M * 16];        // suppression bitmask matrix (512 x 512 bits)
__device__ float    g_scores[N_ANCH];      // fallback path only

// ---------------- decode helper (matches reference _decode) ----------------
__device__ __forceinline__ void decode_box(const float4& rg, const float4& an,
                                           float& y1, float& x1, float& y2, float& x2,
                                           float& ar) {
    float dx = rg.x * 0.1f, dy = rg.y * 0.1f, dw = rg.z * 0.2f, dh = rg.w * 0.2f;
    float xc = dx * an.z + an.x;
    float yc = dy * an.w + an.y;
    float w  = expf(dw) * an.z;
    float h  = expf(dh) * an.w;
    y1 = yc - 0.5f * h;  x1 = xc - 0.5f * w;
    y2 = yc + 0.5f * h;  x2 = xc + 0.5f * w;
    ar = (y2 - y1) * (x2 - x1);
}

__device__ __forceinline__ float iou_f(float ay1, float ax1, float ay2, float ax2, float aar,
                                       float by1, float bx1, float by2, float bx2, float bar) {
    float ih = fmaxf(fminf(ay2, by2) - fmaxf(ay1, by1), 0.f);
    float iw = fmaxf(fminf(ax2, bx2) - fmaxf(ax1, bx1), 0.f);
    float inter = ih * iw;
    return inter / (aar + bar - inter + 1e-12f);
}

// shared gather routine: decode box + landmarks for one output slot
__device__ __forceinline__ void gather_one(int t, int idx, float m,
                                           const float4* __restrict__ reg4,
                                           const float*  __restrict__ lnd,
                                           const float4* __restrict__ anch4,
                                           float* __restrict__ out) {
    float4 rg = __ldg(reg4 + idx);
    float4 an = __ldg(anch4 + idx);
    float y1, x1, y2, x2, ar;
    decode_box(rg, an, y1, x1, y2, x2, ar);
    out[4 * t + 0] = y1 * m;
    out[4 * t + 1] = x1 * m;
    out[4 * t + 2] = y2 * m;
    out[4 * t + 3] = x2 * m;
    const float* lp = lnd + 10 * idx;
    float* op = out + 4 * MAX_OUT + 10 * t;
#pragma unroll
    for (int k = 0; k < 5; k++) {
        float lx = lp[2 * k]     * 0.1f * an.z + an.x;
        float ly = lp[2 * k + 1] * 0.1f * an.w + an.y;
        op[2 * k]     = lx * m;
        op[2 * k + 1] = ly * m;
    }
}

// ---------------- 1) histogram of candidate scores ----------------
__global__ void hist_kernel(const float2* __restrict__ cls, int n) {
    int i = blockIdx.x * blockDim.x + threadIdx.x;
    if (i >= n) return;
    float s = __ldg(&cls[i]).y;
    if (s > NMS_TH) {
        unsigned u = __float_as_uint(s) ^ 0x80000000u;   // monotone map, s>0.4 => large positive
        atomicAdd(&g_hist[u >> SHIFT], 1u);
    }
}

// ---------------- 2) reset ctl, find bit-threshold, zero hist ----------------
__global__ __launch_bounds__(1024) void thresh_kernel() {
    __shared__ unsigned csum[1024];
    unsigned t = threadIdx.x;
    if (t == 0) { g_ctl.ncand = 0; g_ctl.thresh_u = 0; g_ctl.truncated = 0;
                  g_ctl.fallback = 0; g_ctl.nc = 0; }
    unsigned b0 = g_hist[t * 4 + 0], b1 = g_hist[t * 4 + 1];
    unsigned b2 = g_hist[t * 4 + 2], b3 = g_hist[t * 4 + 3];
    csum[t] = b0 + b1 + b2 + b3;
    __syncthreads();
    for (int off = 1; off < 1024; off <<= 1) {           // suffix sums
        unsigned v = (t + off < 1024) ? csum[t + off] : 0u;
        __syncthreads();
        csum[t] += v;
        __syncthreads();
    }
    unsigned total = csum[0];
    unsigned above = (t < 1023) ? csum[t + 1] : 0u;
    if (above < TARGET && csum[t] >= TARGET) {
        unsigned run = above;
        unsigned bins[4] = {b0, b1, b2, b3};
        for (int b = 3; b >= 0; b--) {
            run += bins[b];
            if (run >= TARGET) {
                g_ctl.thresh_u  = (unsigned)(t * 4 + b) << SHIFT;
                g_ctl.truncated = (run < total) ? 1u : 0u;
                break;
            }
        }
    }
    __syncthreads();
    g_hist[t * 4 + 0] = 0; g_hist[t * 4 + 1] = 0;       // self-clean for next replay
    g_hist[t * 4 + 2] = 0; g_hist[t * 4 + 3] = 0;
}

// ---------------- 3) compact candidates above threshold as 64-bit keys ----------------
__global__ void compact_kernel(const float2* __restrict__ cls, int n) {
    int i = blockIdx.x * blockDim.x + threadIdx.x;
    if (i >= n) return;
    float s = __ldg(&cls[i]).y;
    if (s > NMS_TH) {
        unsigned u = __float_as_uint(s) ^ 0x80000000u;
        if (u >= g_ctl.thresh_u) {
            unsigned pos = atomicAdd(&g_ctl.ncand, 1u);
            if (pos < CAP)
                g_ckey[pos] = ((unsigned long long)u << 32) | (unsigned)(~(unsigned)i);
        }
    }
}

// ---------------- 4) rank-scatter sort + decode top-M (multi-SM) ----------------
// rank[c] = #{keys > key_c}; unique keys -> permutation; rank<M entries scattered sorted.
__global__ __launch_bounds__(256) void rank_kernel(const float4* __restrict__ reg4,
                                                   const float4* __restrict__ anch4) {
    __shared__ unsigned long long sk[CAP];
    const int t = threadIdx.x;
    const int gid = blockIdx.x * 256 + t;
    unsigned nc_all = g_ctl.ncand;
    if (gid == 0) {
        if (nc_all > CAP) g_ctl.fallback = 1;            // compaction overflow: exact fallback
        g_ctl.nc = (nc_all < M) ? nc_all : M;
        if (nc_all > M) g_ctl.truncated = 1;
    }
    if (nc_all > CAP) return;
    if ((unsigned)(blockIdx.x * 64) >= nc_all) return;   // whole block out of range
    unsigned ncr = (nc_all + 3u) & ~3u;
    for (int k = t; k < (int)ncr; k += 256)
        sk[k] = (k < (int)nc_all) ? g_ckey[k] : 0ULL;
    __syncthreads();
    int c = gid >> 2, h = gid & 3;                       // 4 threads per candidate
    if (c >= (int)nc_all) return;
    unsigned long long mykey = sk[c];
    int r = 0;
    for (int j = h; j < (int)ncr; j += 4)
        r += (sk[j] > mykey) ? 1 : 0;
    r += __shfl_xor_sync(0xFFFFFFFFu, r, 1);
    r += __shfl_xor_sync(0xFFFFFFFFu, r, 2);
    if (h == 0 && r < M) {
        int idx = (int)(~(unsigned)(mykey & 0xFFFFFFFFull));
        g_sidx[r] = idx;
        float4 rg = __ldg(reg4 + idx);
        float4 an = __ldg(anch4 + idx);
        float y1, x1, y2, x2, ar;
        decode_box(rg, an, y1, x1, y2, x2, ar);
        g_sb4[r] = make_float4(y1, x1, y2, x2);
        g_sar[r] = ar;
    }
    // positions [nc, M) are never written by any run -> stay zero (degenerate boxes, IoU=0)
}

// ---------------- 5) pairwise suppression bitmask (multi-SM) ----------------
__global__ __launch_bounds__(256) void pairs_kernel() {
    __shared__ float4 sb[M];
    __shared__ float  sa[M];
    const int t = threadIdx.x;
    for (int k = t; k < M; k += 256) { sb[k] = g_sb4[k]; sa[k] = g_sar[k]; }
    __syncthreads();
    int gid = blockIdx.x * 256 + t;                      // M rows x 16 words = 8192
    int i = gid >> 4, w = gid & 15;
    float4 bi = sb[i];
    float ai = sa[i];
    unsigned word = 0;
#pragma unroll 8
    for (int jj = 0; jj < 32; jj++) {
        int j = (w << 5) + jj;
        float4 bj = sb[j];
        float iou = iou_f(bi.x, bi.y, bi.z, bi.w, ai, bj.x, bj.y, bj.z, bj.w, sa[j]);
        if (iou > NMS_TH) word |= (1u << jj);
    }
    g_supp[(i << 4) + w] = word;
}

// ---------------- 6) greedy selection (warp-serial) + fused gather ----------------
__global__ __launch_bounds__(256) void greedy_kernel(const float4* __restrict__ reg4,
                                                     const float*  __restrict__ lnd,
                                                     const float4* __restrict__ anch4,
                                                     float* __restrict__ out) {
    __shared__ unsigned ssup[M * 16];
    __shared__ int      ssidx[M];
    __shared__ short    ssel[MAX_OUT];
    __shared__ int      s_nsel;
    if (g_ctl.fallback) return;                          // exact fallback will handle output
    const int t = threadIdx.x;
    for (int k = t; k < M * 16; k += 256) ssup[k] = g_supp[k];
    for (int k = t; k < M; k += 256) ssidx[k] = g_sidx[k];
    unsigned truncated = g_ctl.truncated;
    __syncthreads();

    if (t < 32) {
        const unsigned FULL = 0xFFFFFFFFu;
        int lane = t;
        int nc = (int)g_ctl.nc;
        unsigned valid = 0;
        if (lane < 16) {
            int rem = nc - lane * 32;
            valid = (rem >= 32) ? 0xFFFFFFFFu : ((rem <= 0) ? 0u : ((1u << rem) - 1u));
        }
        unsigned removed = 0;
        int nsel = 0;
        while (nsel < MAX_OUT) {
            unsigned alivew = valid & ~removed;
            unsigned bal = __ballot_sync(FULL, alivew != 0u);
            if (!bal) break;
            int src = __ffs(bal) - 1;
            unsigned w0 = __shfl_sync(FULL, alivew, src);
            int i = (src << 5) + __ffs(w0) - 1;
            if (lane == 0) ssel[nsel] = (short)i;
            if (lane < 16) removed |= ssup[(i << 4) + lane];   // self bit (IoU=1) removes i
            nsel++;
        }
        if (lane == 0) s_nsel = nsel;
    }
    __syncthreads();
    int nsel = s_nsel;
    if (nsel < MAX_OUT && truncated) {                   // working set exhausted -> exact path
        if (t == 0) g_ctl.fallback = 1;
        return;
    }
    if (t < MAX_OUT) {
        bool v = (t < nsel);
        int idx = v ? ssidx[ssel[t]] : 0;
        gather_one(t, idx, v ? 1.f : 0.f, reg4, lnd, anch4, out);
    }
}

// ---------------- 7) exact fallback (normally predicate-off no-op) ----------------
__global__ __launch_bounds__(1024) void fallback_kernel(const float2* __restrict__ cls,
                                                        const float4* __restrict__ reg4,
                                                        const float*  __restrict__ lnd,
                                                        const float4* __restrict__ anch4,
                                                        int n, float* __restrict__ out) {
    if (g_ctl.fallback == 0) return;
    __shared__ float red_s[1024];
    __shared__ int   red_i[1024];
    __shared__ int   s_idx[MAX_OUT];
    __shared__ int   s_val[MAX_OUT];
    const int t = threadIdx.x;
    for (int j = t; j < n; j += 1024) {
        float s = cls[j].y;
        g_scores[j] = (s > NMS_TH) ? s : -INFINITY;
    }
    __syncthreads();
    for (int it = 0; it < MAX_OUT; it++) {
        float best = -INFINITY; int bi = 0;
        for (int j = t; j < n; j += 1024) {
            float v = g_scores[j];
            if (v > best) { best = v; bi = j; }
        }
        red_s[t] = best; red_i[t] = bi;
        __syncthreads();
        for (int s = 512; s > 0; s >>= 1) {
            if (t < s) {
                float vo = red_s[t + s]; int io = red_i[t + s];
                if (vo > red_s[t] || (vo == red_s[t] && io < red_i[t])) {
                    red_s[t] = vo; red_i[t] = io;
                }
            }
            __syncthreads();
        }
        int i = red_i[0];
        bool valid = (red_s[0] > -INFINITY);
        float4 rgi = __ldg(reg4 + i);
        float4 ani = __ldg(anch4 + i);
        float by1, bx1, by2, bx2, bar;
        decode_box(rgi, ani, by1, bx1, by2, bx2, bar);
        if (valid) {
            for (int j = t; j < n; j += 1024) {
                if (g_scores[j] > -INFINITY) {
                    float4 rg = __ldg(reg4 + j);
                    float4 an = __ldg(anch4 + j);
                    float y1, x1, y2, x2, ar;
                    decode_box(rg, an, y1, x1, y2, x2, ar);
                    if (iou_f(y1, x1, y2, x2, ar, by1, bx1, by2, bx2, bar) > NMS_TH)
                        g_scores[j] = -INFINITY;
                }
            }
        }
        if (t == 0) { s_idx[it] = i; s_val[it] = valid ? 1 : 0; }
        __syncthreads();
    }
    if (t < MAX_OUT)
        gather_one(t, s_val[t] ? s_idx[t] : 0, s_val[t] ? 1.f : 0.f, reg4, lnd, anch4, out);
}

// ---------------- launch ----------------
extern "C" void kernel_launch(void* const* d_in, const int* in_sizes, int n_in,
                              void* d_out, int out_size) {
    const float2* cls   = (const float2*)d_in[0];
    const float4* reg4  = (const float4*)d_in[1];
    const float*  lnd   = (const float*)d_in[2];
    const float4* anch4 = (const float4*)d_in[3];
    float* out = (float*)d_out;

    int n = in_sizes[0] / 2;
    if (n > N_ANCH) n = N_ANCH;
    int nb = (n + 255) / 256;

    hist_kernel<<<nb, 256>>>(cls, n);
    thresh_kernel<<<1, 1024>>>();
    compact_kernel<<<nb, 256>>>(cls, n);
    rank_kernel<<<CAP / 64, 256>>>(reg4, anch4);
    pairs_kernel<<<M * 16 / 256, 256>>>();
    greedy_kernel<<<1, 256>>>(reg4, lnd, anch4, out);
    fallback_kernel<<<1, 1024>>>(cls, reg4, lnd, anch4, n, out);
}